// round 5
// baseline (speedup 1.0000x reference)
#include <cuda_runtime.h>
#include <math.h>
#include <stdint.h>

#define LVOX 4096
#define NBATCH 4
#define NB 8          // (branch, batch) pairs
#define MAXN 32       // max neighbors per voxel (analytic bound: <= 27)
#define TPB_A 256
#define ABLK 16       // phase-A blocks per nb
#define TPB_B 512

// Scratch: static device globals (no allocation allowed)
__device__ unsigned long long g_cnt8[LVOX];        // byte nb of word l = cnt(nb,l)
__device__ unsigned short g_nbr[NB][MAXN][LVOX];   // t-major: coalesced over l
__device__ int            g_partial[NB][ABLK];     // per-block pair counts
__device__ double         g_num[NB];
__device__ unsigned int   g_done;

// ───────────────────────── Phase A ─────────────────────────
// Grid (ABLK, NB), 256 threads: one thread per (nb, l).
__global__ void k_phaseA(const float* __restrict__ cq, const float* __restrict__ ck) {
    int nb  = blockIdx.y;
    int l   = blockIdx.x * TPB_A + threadIdx.x;
    int tid = threadIdx.x;
    int br = nb >> 2;
    int n  = nb & 3;
    int qb = br ? (3 - n) : n;     // flipped q-batch for branch 1

    if (blockIdx.x == 0 && tid == 0) {
        g_num[nb] = 0.0;           // consumed only after kernel boundary
        if (nb == 0) g_done = 0u;
    }

    // q crop box (batch qb — flipped for branch 1)
    float q0 = cq[qb*6+0], q1 = cq[qb*6+1], q2 = cq[qb*6+2];
    float bq0 = (cq[qb*6+3] - q0) * (1.0f/16.0f);
    float bq1 = (cq[qb*6+4] - q1) * (1.0f/16.0f);
    float bq2 = (cq[qb*6+5] - q2) * (1.0f/16.0f);
    // k crop box (batch n)
    float k0 = ck[n*6+0], k1 = ck[n*6+1], k2 = ck[n*6+2];
    float bk0 = (ck[n*6+3] - k0) * (1.0f/16.0f);
    float bk1 = (ck[n*6+4] - k1) * (1.0f/16.0f);
    float bk2 = (ck[n*6+5] - k2) * (1.0f/16.0f);

    // max_diag uses UNFLIPPED diag_q[n], diag_k[n]
    float a0 = (cq[n*6+3] - cq[n*6+0]) * (1.0f/16.0f);
    float a1 = (cq[n*6+4] - cq[n*6+1]) * (1.0f/16.0f);
    float a2 = (cq[n*6+5] - cq[n*6+2]) * (1.0f/16.0f);
    float diagq = sqrtf((a0*a0 + a1*a1) + a2*a2);
    float diagk = sqrtf((bk0*bk0 + bk1*bk1) + bk2*bk2);
    float md = fmaxf(diagq, diagk);
    float R  = 0.5f * md;

    int i  = l >> 8;
    int j  = (l >> 4) & 15;
    int kz = l & 15;
    float cx = fmaf((float)i  + 0.5f, bq0, q0);
    float cy = fmaf((float)j  + 0.5f, bq1, q1);
    float cz = fmaf((float)kz + 0.5f, bq2, q2);

    int xlo = max(0,  (int)floorf((cx - R - k0) / bk0 - 0.5f));
    int xhi = min(15, (int)ceilf ((cx + R - k0) / bk0 - 0.5f));
    int ylo = max(0,  (int)floorf((cy - R - k1) / bk1 - 0.5f));
    int yhi = min(15, (int)ceilf ((cy + R - k1) / bk1 - 0.5f));
    int zlo = max(0,  (int)floorf((cz - R - k2) / bk2 - 0.5f));
    int zhi = min(15, (int)ceilf ((cz + R - k2) / bk2 - 0.5f));

    int cnt = 0;
    for (int jx = xlo; jx <= xhi; jx++) {
        float dx = cx - fmaf((float)jx + 0.5f, bk0, k0);
        for (int jy = ylo; jy <= yhi; jy++) {
            float dy = cy - fmaf((float)jy + 0.5f, bk1, k1);
            for (int jz = zlo; jz <= zhi; jz++) {
                float dz = cz - fmaf((float)jz + 0.5f, bk2, k2);
                float d2 = dx*dx + dy*dy + dz*dz;
                // Exact reference semantics: sqrt then divide then compare
                if (sqrtf(d2) / md < 0.5f) {
                    if (cnt < MAXN)
                        g_nbr[nb][cnt][l] = (unsigned short)(jx*256 + jy*16 + jz);
                    cnt++;
                }
            }
        }
    }
    if (cnt > MAXN) cnt = MAXN;
    // Byte-granular store into the packed count word (distinct byte per nb)
    ((unsigned char*)&g_cnt8[l])[nb] = (unsigned char)cnt;

    // Block-reduce pair count into g_partial
    __shared__ int red[TPB_A / 32];
    int mc = cnt;
    for (int o = 16; o; o >>= 1) mc += __shfl_down_sync(0xFFFFFFFFu, mc, o);
    if ((tid & 31) == 0) red[tid >> 5] = mc;
    __syncthreads();
    if (tid == 0) {
        int s = 0;
        for (int w = 0; w < TPB_A / 32; w++) s += red[w];
        g_partial[nb][blockIdx.x] = s;
    }
}

// ───────────────────────── Phase B (+ fused finalize) ─────────────────────────
// Block = (channel c, batch-pair p). Pair p=0 -> (n=0,n'=3), p=1 -> (n=1,n'=2).
// Stages one k channel from each batch of the pair; q rows read exactly once.
// Covers all four (branch,batch) dot products of the pair:
//   A: g_num[n]    += q[n]  · gather(kn, list n)
//   B: g_num[4+n'] += q[n]  · gather(kp, list 4+n')
//   C: g_num[n']   += q[n'] · gather(kp, list n')
//   D: g_num[4+n]  += q[n'] · gather(kn, list 4+n)
__global__ void __launch_bounds__(TPB_B, 4)
k_phaseB(const float* __restrict__ q, const float* __restrict__ k,
         float* __restrict__ out, int nblocks) {
    int c   = blockIdx.x;          // 0..319
    int p   = blockIdx.y;          // 0..1
    int n   = p;                   // 0 or 1
    int np  = 3 - p;               // 3 or 2
    int tid = threadIdx.x;

    __shared__ float kn[LVOX];
    __shared__ float kp[LVOX];

    const float4* krn = (const float4*)(k + ((size_t)n  * 320 + c) * (size_t)LVOX);
    const float4* krp = (const float4*)(k + ((size_t)np * 320 + c) * (size_t)LVOX);
    for (int i = tid; i < LVOX / 4; i += TPB_B) {
        ((float4*)kn)[i] = krn[i];
        ((float4*)kp)[i] = krp[i];
    }
    __syncthreads();

    const float* qn = q + ((size_t)n  * 320 + c) * (size_t)LVOX;
    const float* qp = q + ((size_t)np * 320 + c) * (size_t)LVOX;

    int nbA = n, nbB = 4 + np, nbC = np, nbD = 4 + n;
    float accA = 0.f, accB = 0.f, accC = 0.f, accD = 0.f;

    for (int l = tid; l < LVOX; l += TPB_B) {
        unsigned long long v = g_cnt8[l];
        int cA = (int)((v >> (8 * nbA)) & 0xFF);
        int cB = (int)((v >> (8 * nbB)) & 0xFF);
        int cC = (int)((v >> (8 * nbC)) & 0xFF);
        int cD = (int)((v >> (8 * nbD)) & 0xFF);

        float sA = 0.f, sB = 0.f, sC = 0.f, sD = 0.f;
        for (int t = 0; t < cA; t++) sA += kn[g_nbr[nbA][t][l]];
        for (int t = 0; t < cB; t++) sB += kp[g_nbr[nbB][t][l]];
        for (int t = 0; t < cC; t++) sC += kp[g_nbr[nbC][t][l]];
        for (int t = 0; t < cD; t++) sD += kn[g_nbr[nbD][t][l]];

        float qv  = qn[l];
        float qv2 = qp[l];
        accA = fmaf(qv,  sA, accA);
        accB = fmaf(qv,  sB, accB);
        accC = fmaf(qv2, sC, accC);
        accD = fmaf(qv2, sD, accD);
    }

    // Reduce the four accumulators (double for determinism-insensitive accuracy)
    double tA = accA, tB = accB, tC = accC, tD = accD;
    for (int o = 16; o; o >>= 1) {
        tA += __shfl_down_sync(0xFFFFFFFFu, tA, o);
        tB += __shfl_down_sync(0xFFFFFFFFu, tB, o);
        tC += __shfl_down_sync(0xFFFFFFFFu, tC, o);
        tD += __shfl_down_sync(0xFFFFFFFFu, tD, o);
    }
    __shared__ double rA[TPB_B / 32], rB[TPB_B / 32], rC[TPB_B / 32], rD[TPB_B / 32];
    if ((tid & 31) == 0) {
        int w = tid >> 5;
        rA[w] = tA; rB[w] = tB; rC[w] = tC; rD[w] = tD;
    }
    __syncthreads();
    if (tid == 0) {
        double sA = 0.0, sB = 0.0, sC = 0.0, sD = 0.0;
        for (int w = 0; w < TPB_B / 32; w++) {
            sA += rA[w]; sB += rB[w]; sC += rC[w]; sD += rD[w];
        }
        atomicAdd(&g_num[nbA], sA);
        atomicAdd(&g_num[nbB], sB);
        atomicAdd(&g_num[nbC], sC);
        atomicAdd(&g_num[nbD], sD);
        __threadfence();
        unsigned int ticket = atomicAdd(&g_done, 1u);
        if (ticket == (unsigned int)(nblocks - 1)) {
            // Last block finalizes (all prior g_num adds fenced-visible).
            double a = 0.0, b = 0.0;
            for (int m = 0; m < NBATCH; m++) {
                int tot0 = 0, tot1 = 0;
                for (int w = 0; w < ABLK; w++) {
                    tot0 += g_partial[m][w];
                    tot1 += g_partial[4 + m][w];
                }
                a += g_num[m]     / ((double)tot0 + 1e-6);
                b += g_num[4 + m] / ((double)tot1 + 1e-6);
            }
            out[0] = (float)(-2.0 * (a / 4.0) - 2.0 * (b / 4.0));
        }
    }
}

extern "C" void kernel_launch(void* const* d_in, const int* in_sizes, int n_in,
                              void* d_out, int out_size) {
    const float* q  = (const float*)d_in[0];
    const float* k  = (const float*)d_in[1];
    const float* cq = (const float*)d_in[2];
    const float* ck = (const float*)d_in[3];

    dim3 ga(ABLK, NB);
    k_phaseA<<<ga, TPB_A>>>(cq, ck);
    dim3 gb(320, 2);   // 640 blocks: channel x batch-pair
    k_phaseB<<<gb, TPB_B>>>(q, k, (float*)d_out, 640);
}

// round 6
// speedup vs baseline: 1.3371x; 1.3371x over previous
#include <cuda_runtime.h>
#include <math.h>
#include <stdint.h>

#define LVOX 4096
#define NBATCH 4
#define NB 8          // (branch, batch) pairs
#define MAXN 32       // max neighbors per voxel (analytic bound: <= 27)
#define CPB 4         // channels per phase-B block
#define TPB_A 256
#define ABLK 16       // phase-A blocks per nb
#define TPB_B 512

// Scratch: static device globals (no allocation allowed)
__device__ unsigned long long g_cnt8[LVOX];        // byte nb of word l = cnt(nb,l)
__device__ unsigned short g_nbr[NB][MAXN][LVOX];   // t-major: coalesced over l
__device__ int            g_partial[NB][ABLK];     // per-block pair counts
__device__ double         g_num[NB];
__device__ unsigned int   g_done;

// ───────────────────────── Phase A ─────────────────────────
// Grid (ABLK, NB), 256 threads: one thread per (nb, l).
__global__ void k_phaseA(const float* __restrict__ cq, const float* __restrict__ ck) {
    int nb  = blockIdx.y;
    int l   = blockIdx.x * TPB_A + threadIdx.x;
    int tid = threadIdx.x;
    int br = nb >> 2;
    int n  = nb & 3;
    int qb = br ? (3 - n) : n;     // flipped q-batch for branch 1

    if (blockIdx.x == 0 && tid == 0) {
        g_num[nb] = 0.0;           // consumed only after kernel boundary
        if (nb == 0) g_done = 0u;
    }

    // q crop box (batch qb — flipped for branch 1)
    float q0 = cq[qb*6+0], q1 = cq[qb*6+1], q2 = cq[qb*6+2];
    float bq0 = (cq[qb*6+3] - q0) * (1.0f/16.0f);
    float bq1 = (cq[qb*6+4] - q1) * (1.0f/16.0f);
    float bq2 = (cq[qb*6+5] - q2) * (1.0f/16.0f);
    // k crop box (batch n)
    float k0 = ck[n*6+0], k1 = ck[n*6+1], k2 = ck[n*6+2];
    float bk0 = (ck[n*6+3] - k0) * (1.0f/16.0f);
    float bk1 = (ck[n*6+4] - k1) * (1.0f/16.0f);
    float bk2 = (ck[n*6+5] - k2) * (1.0f/16.0f);

    // max_diag uses UNFLIPPED diag_q[n], diag_k[n]
    float a0 = (cq[n*6+3] - cq[n*6+0]) * (1.0f/16.0f);
    float a1 = (cq[n*6+4] - cq[n*6+1]) * (1.0f/16.0f);
    float a2 = (cq[n*6+5] - cq[n*6+2]) * (1.0f/16.0f);
    float diagq = sqrtf((a0*a0 + a1*a1) + a2*a2);
    float diagk = sqrtf((bk0*bk0 + bk1*bk1) + bk2*bk2);
    float md = fmaxf(diagq, diagk);
    float R  = 0.5f * md;

    int i  = l >> 8;
    int j  = (l >> 4) & 15;
    int kz = l & 15;
    float cx = fmaf((float)i  + 0.5f, bq0, q0);
    float cy = fmaf((float)j  + 0.5f, bq1, q1);
    float cz = fmaf((float)kz + 0.5f, bq2, q2);

    int xlo = max(0,  (int)floorf((cx - R - k0) / bk0 - 0.5f));
    int xhi = min(15, (int)ceilf ((cx + R - k0) / bk0 - 0.5f));
    int ylo = max(0,  (int)floorf((cy - R - k1) / bk1 - 0.5f));
    int yhi = min(15, (int)ceilf ((cy + R - k1) / bk1 - 0.5f));
    int zlo = max(0,  (int)floorf((cz - R - k2) / bk2 - 0.5f));
    int zhi = min(15, (int)ceilf ((cz + R - k2) / bk2 - 0.5f));

    int cnt = 0;
    for (int jx = xlo; jx <= xhi; jx++) {
        float dx = cx - fmaf((float)jx + 0.5f, bk0, k0);
        for (int jy = ylo; jy <= yhi; jy++) {
            float dy = cy - fmaf((float)jy + 0.5f, bk1, k1);
            for (int jz = zlo; jz <= zhi; jz++) {
                float dz = cz - fmaf((float)jz + 0.5f, bk2, k2);
                float d2 = dx*dx + dy*dy + dz*dz;
                // Exact reference semantics: sqrt then divide then compare
                if (sqrtf(d2) / md < 0.5f) {
                    if (cnt < MAXN)
                        g_nbr[nb][cnt][l] = (unsigned short)(jx*256 + jy*16 + jz);
                    cnt++;
                }
            }
        }
    }
    if (cnt > MAXN) cnt = MAXN;
    // Byte-granular store into the packed count word (distinct byte per nb)
    ((unsigned char*)&g_cnt8[l])[nb] = (unsigned char)cnt;

    // Block-reduce pair count into g_partial
    __shared__ int red[TPB_A / 32];
    int mc = cnt;
    for (int o = 16; o; o >>= 1) mc += __shfl_down_sync(0xFFFFFFFFu, mc, o);
    if ((tid & 31) == 0) red[tid >> 5] = mc;
    __syncthreads();
    if (tid == 0) {
        int s = 0;
        for (int w = 0; w < TPB_A / 32; w++) s += red[w];
        g_partial[nb][blockIdx.x] = s;
    }
}

// ───────────────────────── Phase B (+ fused finalize) ─────────────────────────
// Block = (channel chunk, batch n, l-half). Stages k[n] channels TRANSPOSED as
// float4 per voxel: one LDS.128 per gather entry serves all CPB channels.
// Handles BOTH branches for n over its half of the l-range.
__global__ void __launch_bounds__(TPB_B, 3)
k_phaseB(const float* __restrict__ q, const float* __restrict__ k,
         float* __restrict__ out, int nblocks) {
    int cchunk = blockIdx.x;   // 0..79
    int n      = blockIdx.y;   // 0..3
    int half   = blockIdx.z;   // 0..1
    int c0     = cchunk * CPB;
    extern __shared__ float4 kk4[];   // [LVOX] = 64KB, kk4[m] = k channels c0..c0+3 at m
    int tid = threadIdx.x;

    // Stage k transposed (4 coalesced channel streams -> STS.128)
    {
        const float* kp = k + ((size_t)n * 320 + c0) * (size_t)LVOX;
        for (int i = tid; i < LVOX; i += TPB_B)
            kk4[i] = make_float4(kp[i], kp[LVOX + i], kp[2 * LVOX + i], kp[3 * LVOX + i]);
    }
    __syncthreads();

    int nb0 = n, nb1 = 4 + n;
    const float* qn = q + ((size_t)n       * 320 + c0) * (size_t)LVOX;
    const float* qf = q + ((size_t)(3 - n) * 320 + c0) * (size_t)LVOX;

    float4 acc0 = {0.f,0.f,0.f,0.f};
    float4 acc1 = {0.f,0.f,0.f,0.f};

    int lbase = half * (LVOX / 2);
    int lend  = lbase + (LVOX / 2);
    for (int l = lbase + tid; l < lend; l += TPB_B) {     // 4 iterations
        unsigned long long v = g_cnt8[l];
        int cnt0 = (int)((v >> (8 * nb0)) & 0xFF);
        int cnt1 = (int)((v >> (8 * nb1)) & 0xFF);

        float4 s0 = {0.f,0.f,0.f,0.f};
        for (int t = 0; t < cnt0; t++) {
            float4 kv = kk4[g_nbr[nb0][t][l]];
            s0.x += kv.x; s0.y += kv.y; s0.z += kv.z; s0.w += kv.w;
        }
        float4 s1 = {0.f,0.f,0.f,0.f};
        for (int t = 0; t < cnt1; t++) {
            float4 kv = kk4[g_nbr[nb1][t][l]];
            s1.x += kv.x; s1.y += kv.y; s1.z += kv.z; s1.w += kv.w;
        }

        if (cnt0) {
            acc0.x = fmaf(qn[0 * LVOX + l], s0.x, acc0.x);
            acc0.y = fmaf(qn[1 * LVOX + l], s0.y, acc0.y);
            acc0.z = fmaf(qn[2 * LVOX + l], s0.z, acc0.z);
            acc0.w = fmaf(qn[3 * LVOX + l], s0.w, acc0.w);
        }
        if (cnt1) {
            acc1.x = fmaf(qf[0 * LVOX + l], s1.x, acc1.x);
            acc1.y = fmaf(qf[1 * LVOX + l], s1.y, acc1.y);
            acc1.z = fmaf(qf[2 * LVOX + l], s1.z, acc1.z);
            acc1.w = fmaf(qf[3 * LVOX + l], s1.w, acc1.w);
        }
    }

    double t0 = (double)acc0.x + (double)acc0.y + (double)acc0.z + (double)acc0.w;
    double t1 = (double)acc1.x + (double)acc1.y + (double)acc1.z + (double)acc1.w;
    for (int o = 16; o; o >>= 1) {
        t0 += __shfl_down_sync(0xFFFFFFFFu, t0, o);
        t1 += __shfl_down_sync(0xFFFFFFFFu, t1, o);
    }
    __shared__ double red0[TPB_B / 32], red1[TPB_B / 32];
    if ((tid & 31) == 0) { red0[tid >> 5] = t0; red1[tid >> 5] = t1; }
    __syncthreads();
    if (tid == 0) {
        double s0 = 0.0, s1 = 0.0;
        for (int w = 0; w < TPB_B / 32; w++) { s0 += red0[w]; s1 += red1[w]; }
        atomicAdd(&g_num[nb0], s0);
        atomicAdd(&g_num[nb1], s1);
        __threadfence();
        unsigned int ticket = atomicAdd(&g_done, 1u);
        if (ticket == (unsigned int)(nblocks - 1)) {
            // Last block finalizes (all prior g_num adds fenced-visible).
            double a = 0.0, b = 0.0;
            for (int m = 0; m < NBATCH; m++) {
                int tot0 = 0, tot1 = 0;
                for (int w = 0; w < ABLK; w++) {
                    tot0 += g_partial[m][w];
                    tot1 += g_partial[4 + m][w];
                }
                a += g_num[m]     / ((double)tot0 + 1e-6);
                b += g_num[4 + m] / ((double)tot1 + 1e-6);
            }
            out[0] = (float)(-2.0 * (a / 4.0) - 2.0 * (b / 4.0));
        }
    }
}

extern "C" void kernel_launch(void* const* d_in, const int* in_sizes, int n_in,
                              void* d_out, int out_size) {
    const float* q  = (const float*)d_in[0];
    const float* k  = (const float*)d_in[1];
    const float* cq = (const float*)d_in[2];
    const float* ck = (const float*)d_in[3];

    (void)cudaFuncSetAttribute(k_phaseB, cudaFuncAttributeMaxDynamicSharedMemorySize,
                               LVOX * (int)sizeof(float4));

    dim3 ga(ABLK, NB);
    k_phaseA<<<ga, TPB_A>>>(cq, ck);
    dim3 gb(320 / CPB, NBATCH, 2);   // 640 blocks: chunk x batch x l-half
    k_phaseB<<<gb, TPB_B, LVOX * (int)sizeof(float4)>>>(q, k, (float*)d_out, 640);
}

// round 7
// speedup vs baseline: 1.5777x; 1.1799x over previous
#include <cuda_runtime.h>
#include <math.h>
#include <stdint.h>

#define LVOX 4096
#define NBATCH 4
#define NB 8          // (branch, batch) pairs
#define MAXN 32       // max neighbors per voxel (analytic bound: <= 27)
#define CPB 4         // channels per phase-B block
#define TPB_A 256
#define ABLK 16       // phase-A blocks per nb
#define TPB_B 512

// Scratch: static device globals (no allocation allowed)
__device__ unsigned char  g_cntb[NB][LVOX];        // cnt(nb,l) as byte
__device__ unsigned short g_nbr[NB][MAXN][LVOX];   // PRE-SWIZZLED idx m'=((m&3)<<10)|(m>>2)
__device__ int            g_partial[NB][ABLK];     // per-block pair counts
__device__ double         g_num[NB];
__device__ unsigned int   g_done;

// ───────────────────────── Phase A ─────────────────────────
__global__ void k_phaseA(const float* __restrict__ cq, const float* __restrict__ ck) {
    int nb  = blockIdx.y;
    int l   = blockIdx.x * TPB_A + threadIdx.x;
    int tid = threadIdx.x;
    int br = nb >> 2;
    int n  = nb & 3;
    int qb = br ? (3 - n) : n;     // flipped q-batch for branch 1

    if (blockIdx.x == 0 && tid == 0) {
        g_num[nb] = 0.0;           // consumed only after kernel boundary
        if (nb == 0) g_done = 0u;
    }

    float q0 = cq[qb*6+0], q1 = cq[qb*6+1], q2 = cq[qb*6+2];
    float bq0 = (cq[qb*6+3] - q0) * (1.0f/16.0f);
    float bq1 = (cq[qb*6+4] - q1) * (1.0f/16.0f);
    float bq2 = (cq[qb*6+5] - q2) * (1.0f/16.0f);
    float k0 = ck[n*6+0], k1 = ck[n*6+1], k2 = ck[n*6+2];
    float bk0 = (ck[n*6+3] - k0) * (1.0f/16.0f);
    float bk1 = (ck[n*6+4] - k1) * (1.0f/16.0f);
    float bk2 = (ck[n*6+5] - k2) * (1.0f/16.0f);

    // max_diag uses UNFLIPPED diag_q[n], diag_k[n]
    float a0 = (cq[n*6+3] - cq[n*6+0]) * (1.0f/16.0f);
    float a1 = (cq[n*6+4] - cq[n*6+1]) * (1.0f/16.0f);
    float a2 = (cq[n*6+5] - cq[n*6+2]) * (1.0f/16.0f);
    float diagq = sqrtf((a0*a0 + a1*a1) + a2*a2);
    float diagk = sqrtf((bk0*bk0 + bk1*bk1) + bk2*bk2);
    float md = fmaxf(diagq, diagk);
    float R  = 0.5f * md;

    int i  = l >> 8;
    int j  = (l >> 4) & 15;
    int kz = l & 15;
    float cx = fmaf((float)i  + 0.5f, bq0, q0);
    float cy = fmaf((float)j  + 0.5f, bq1, q1);
    float cz = fmaf((float)kz + 0.5f, bq2, q2);

    int xlo = max(0,  (int)floorf((cx - R - k0) / bk0 - 0.5f));
    int xhi = min(15, (int)ceilf ((cx + R - k0) / bk0 - 0.5f));
    int ylo = max(0,  (int)floorf((cy - R - k1) / bk1 - 0.5f));
    int yhi = min(15, (int)ceilf ((cy + R - k1) / bk1 - 0.5f));
    int zlo = max(0,  (int)floorf((cz - R - k2) / bk2 - 0.5f));
    int zhi = min(15, (int)ceilf ((cz + R - k2) / bk2 - 0.5f));

    int cnt = 0;
    for (int jx = xlo; jx <= xhi; jx++) {
        float dx = cx - fmaf((float)jx + 0.5f, bk0, k0);
        for (int jy = ylo; jy <= yhi; jy++) {
            float dy = cy - fmaf((float)jy + 0.5f, bk1, k1);
            for (int jz = zlo; jz <= zhi; jz++) {
                float dz = cz - fmaf((float)jz + 0.5f, bk2, k2);
                float d2 = dx*dx + dy*dy + dz*dz;
                // Exact reference semantics: sqrt then divide then compare
                if (sqrtf(d2) / md < 0.5f) {
                    if (cnt < MAXN) {
                        int m = jx*256 + jy*16 + jz;
                        // pre-swizzle for quartered smem layout in phase B
                        g_nbr[nb][cnt][l] = (unsigned short)(((m & 3) << 10) | (m >> 2));
                    }
                    cnt++;
                }
            }
        }
    }
    if (cnt > MAXN) cnt = MAXN;
    g_cntb[nb][l] = (unsigned char)cnt;

    __shared__ int red[TPB_A / 32];
    int mc = cnt;
    for (int o = 16; o; o >>= 1) mc += __shfl_down_sync(0xFFFFFFFFu, mc, o);
    if ((tid & 31) == 0) red[tid >> 5] = mc;
    __syncthreads();
    if (tid == 0) {
        int s = 0;
        for (int w = 0; w < TPB_A / 32; w++) s += red[w];
        g_partial[nb][blockIdx.x] = s;
    }
}

// ───────────────────────── Phase B (+ fused finalize) ─────────────────────────
// Block = (channel chunk, batch n). smem holds k[n] channels c0..c0+3 transposed,
// QUARTERED: kk4[(m&3)*1024 + (m>>2)] = float4{k_c0[m],..,k_c3[m]}; gather uses
// the pre-swizzled index from g_nbr directly. Thread handles groups of 4
// consecutive l -> vector loads for q (LDG.128), counts (uchar4), lists (ushort4).
__global__ void __launch_bounds__(TPB_B, 3)
k_phaseB(const float* __restrict__ q, const float* __restrict__ k,
         float* __restrict__ out, int nblocks) {
    int cchunk = blockIdx.x;   // 0..79
    int n      = blockIdx.y;   // 0..3
    int c0     = cchunk * CPB;
    extern __shared__ float4 kk4[];   // [4][1024] quartered transposed tile = 64KB
    int tid = threadIdx.x;

    // Stage: float4 loads per channel, conflict-free quartered stores
    {
        const float4* kc0 = (const float4*)(k + ((size_t)n * 320 + c0 + 0) * (size_t)LVOX);
        const float4* kc1 = (const float4*)(k + ((size_t)n * 320 + c0 + 1) * (size_t)LVOX);
        const float4* kc2 = (const float4*)(k + ((size_t)n * 320 + c0 + 2) * (size_t)LVOX);
        const float4* kc3 = (const float4*)(k + ((size_t)n * 320 + c0 + 3) * (size_t)LVOX);
        for (int g = tid; g < LVOX / 4; g += TPB_B) {   // 2 passes
            float4 a = kc0[g], b = kc1[g], c = kc2[g], d = kc3[g];
            kk4[g]        = make_float4(a.x, b.x, c.x, d.x);  // m = 4g+0
            kk4[1024 + g] = make_float4(a.y, b.y, c.y, d.y);  // m = 4g+1
            kk4[2048 + g] = make_float4(a.z, b.z, c.z, d.z);  // m = 4g+2
            kk4[3072 + g] = make_float4(a.w, b.w, c.w, d.w);  // m = 4g+3
        }
    }
    __syncthreads();

    int nb0 = n, nb1 = 4 + n;
    const float* qn = q + ((size_t)n       * 320 + c0) * (size_t)LVOX;
    const float* qf = q + ((size_t)(3 - n) * 320 + c0) * (size_t)LVOX;
    const uchar4* cb0 = (const uchar4*)g_cntb[nb0];
    const uchar4* cb1 = (const uchar4*)g_cntb[nb1];

    float acc0[4] = {0.f, 0.f, 0.f, 0.f};   // per-channel accumulators, branch 0
    float acc1[4] = {0.f, 0.f, 0.f, 0.f};   // branch 1

    for (int G = tid; G < LVOX / 4; G += TPB_B) {   // 2 groups of 4 l's
        int l4 = G * 4;

        // ---- branch 0 ----
        {
            uchar4 cv = cb0[G];
            int cm = max(max((int)cv.x, (int)cv.y), max((int)cv.z, (int)cv.w));
            float4 s0 = {0,0,0,0}, s1 = {0,0,0,0}, s2 = {0,0,0,0}, s3 = {0,0,0,0};
            for (int t = 0; t < cm; t++) {
                ushort4 mm = *(const ushort4*)&g_nbr[nb0][t][l4];
                if (t < (int)cv.x) { float4 kv = kk4[mm.x]; s0.x += kv.x; s0.y += kv.y; s0.z += kv.z; s0.w += kv.w; }
                if (t < (int)cv.y) { float4 kv = kk4[mm.y]; s1.x += kv.x; s1.y += kv.y; s1.z += kv.z; s1.w += kv.w; }
                if (t < (int)cv.z) { float4 kv = kk4[mm.z]; s2.x += kv.x; s2.y += kv.y; s2.z += kv.z; s2.w += kv.w; }
                if (t < (int)cv.w) { float4 kv = kk4[mm.w]; s3.x += kv.x; s3.y += kv.y; s3.z += kv.z; s3.w += kv.w; }
            }
            if (cm) {
                float4 qv;
                qv = ((const float4*)(qn + 0 * LVOX))[G];
                acc0[0] += qv.x*s0.x + qv.y*s1.x + qv.z*s2.x + qv.w*s3.x;
                qv = ((const float4*)(qn + 1 * LVOX))[G];
                acc0[1] += qv.x*s0.y + qv.y*s1.y + qv.z*s2.y + qv.w*s3.y;
                qv = ((const float4*)(qn + 2 * LVOX))[G];
                acc0[2] += qv.x*s0.z + qv.y*s1.z + qv.z*s2.z + qv.w*s3.z;
                qv = ((const float4*)(qn + 3 * LVOX))[G];
                acc0[3] += qv.x*s0.w + qv.y*s1.w + qv.z*s2.w + qv.w*s3.w;
            }
        }
        // ---- branch 1 ----
        {
            uchar4 cv = cb1[G];
            int cm = max(max((int)cv.x, (int)cv.y), max((int)cv.z, (int)cv.w));
            float4 s0 = {0,0,0,0}, s1 = {0,0,0,0}, s2 = {0,0,0,0}, s3 = {0,0,0,0};
            for (int t = 0; t < cm; t++) {
                ushort4 mm = *(const ushort4*)&g_nbr[nb1][t][l4];
                if (t < (int)cv.x) { float4 kv = kk4[mm.x]; s0.x += kv.x; s0.y += kv.y; s0.z += kv.z; s0.w += kv.w; }
                if (t < (int)cv.y) { float4 kv = kk4[mm.y]; s1.x += kv.x; s1.y += kv.y; s1.z += kv.z; s1.w += kv.w; }
                if (t < (int)cv.z) { float4 kv = kk4[mm.z]; s2.x += kv.x; s2.y += kv.y; s2.z += kv.z; s2.w += kv.w; }
                if (t < (int)cv.w) { float4 kv = kk4[mm.w]; s3.x += kv.x; s3.y += kv.y; s3.z += kv.z; s3.w += kv.w; }
            }
            if (cm) {
                float4 qv;
                qv = ((const float4*)(qf + 0 * LVOX))[G];
                acc1[0] += qv.x*s0.x + qv.y*s1.x + qv.z*s2.x + qv.w*s3.x;
                qv = ((const float4*)(qf + 1 * LVOX))[G];
                acc1[1] += qv.x*s0.y + qv.y*s1.y + qv.z*s2.y + qv.w*s3.y;
                qv = ((const float4*)(qf + 2 * LVOX))[G];
                acc1[2] += qv.x*s0.z + qv.y*s1.z + qv.z*s2.z + qv.w*s3.z;
                qv = ((const float4*)(qf + 3 * LVOX))[G];
                acc1[3] += qv.x*s0.w + qv.y*s1.w + qv.z*s2.w + qv.w*s3.w;
            }
        }
    }

    double t0 = (double)acc0[0] + (double)acc0[1] + (double)acc0[2] + (double)acc0[3];
    double t1 = (double)acc1[0] + (double)acc1[1] + (double)acc1[2] + (double)acc1[3];
    for (int o = 16; o; o >>= 1) {
        t0 += __shfl_down_sync(0xFFFFFFFFu, t0, o);
        t1 += __shfl_down_sync(0xFFFFFFFFu, t1, o);
    }
    __shared__ double red0[TPB_B / 32], red1[TPB_B / 32];
    if ((tid & 31) == 0) { red0[tid >> 5] = t0; red1[tid >> 5] = t1; }
    __syncthreads();
    if (tid == 0) {
        double s0 = 0.0, s1 = 0.0;
        for (int w = 0; w < TPB_B / 32; w++) { s0 += red0[w]; s1 += red1[w]; }
        atomicAdd(&g_num[nb0], s0);
        atomicAdd(&g_num[nb1], s1);
        __threadfence();
        unsigned int ticket = atomicAdd(&g_done, 1u);
        if (ticket == (unsigned int)(nblocks - 1)) {
            double a = 0.0, b = 0.0;
            for (int m = 0; m < NBATCH; m++) {
                int tot0 = 0, tot1 = 0;
                for (int w = 0; w < ABLK; w++) {
                    tot0 += g_partial[m][w];
                    tot1 += g_partial[4 + m][w];
                }
                a += g_num[m]     / ((double)tot0 + 1e-6);
                b += g_num[4 + m] / ((double)tot1 + 1e-6);
            }
            out[0] = (float)(-2.0 * (a / 4.0) - 2.0 * (b / 4.0));
        }
    }
}

extern "C" void kernel_launch(void* const* d_in, const int* in_sizes, int n_in,
                              void* d_out, int out_size) {
    const float* q  = (const float*)d_in[0];
    const float* k  = (const float*)d_in[1];
    const float* cq = (const float*)d_in[2];
    const float* ck = (const float*)d_in[3];

    (void)cudaFuncSetAttribute(k_phaseB, cudaFuncAttributeMaxDynamicSharedMemorySize,
                               LVOX * (int)sizeof(float4));

    dim3 ga(ABLK, NB);
    k_phaseA<<<ga, TPB_A>>>(cq, ck);
    dim3 gb(320 / CPB, NBATCH);   // 320 blocks, one wave at 3 CTAs/SM
    k_phaseB<<<gb, TPB_B, LVOX * (int)sizeof(float4)>>>(q, k, (float*)d_out, 320);
}